// round 6
// baseline (speedup 1.0000x reference)
#include <cuda_runtime.h>

#define N_NODES 16384
#define SZ 128
typedef unsigned long long ull;

// ---------------- f32x2 packed helpers (sm_103a) ----------------
__device__ __forceinline__ ull ffma2(ull a, ull b, ull c) {
    ull d;
    asm("fma.rn.f32x2 %0, %1, %2, %3;" : "=l"(d) : "l"(a), "l"(b), "l"(c));
    return d;
}
__device__ __forceinline__ ull pack2(float x, float y) {
    ull d;
    asm("mov.b64 %0, {%1, %2};" : "=l"(d) : "f"(x), "f"(y));
    return d;
}
__device__ __forceinline__ float2 unpack2(ull v) {
    float2 r;
    asm("mov.b64 {%0, %1}, %2;" : "=f"(r.x), "=f"(r.y) : "l"(v));
    return r;
}

// ---------------- scratch ----------------
__device__ float g_h1[N_NODES * SZ];
__device__ float g_h2[N_NODES * SZ];
__device__ float g_msg[N_NODES * SZ];
__device__ float g_q[N_NODES * SZ];
__device__ float g_mk[N_NODES * SZ];
__device__ float g_mv[N_NODES * SZ];
__device__ float g_att[N_NODES * SZ];

// ---------------- GEMM: C[N,128] = f(A[N,128]@W[128,128]+b)(+add), f32x2 math
// BM=32, BN=128, BK=32, 256 threads; thread: 4 rows (2 pairs) x 4 cols.
template <int RELU_IN, int RELU_OUT, int HAS_BIAS, int HAS_ADD>
__global__ __launch_bounds__(256) void gemm128(
    const float* __restrict__ A, const float* __restrict__ W,
    const float* __restrict__ bias, const float* __restrict__ add,
    float* __restrict__ C)
{
    __shared__ __align__(16) float As[32 * 32];    // [k][row]
    __shared__ __align__(16) float Ws[32 * 128];   // [k][col]
    const int t = threadIdx.x;
    const int tx = t & 31;
    const int ty = t >> 5;
    const int row0 = blockIdx.x * 32;

    ull acc[2][4];
#pragma unroll
    for (int rp = 0; rp < 2; rp++)
#pragma unroll
        for (int c = 0; c < 4; c++) acc[rp][c] = 0ull;

    for (int kt = 0; kt < 4; kt++) {
        const int kk0 = kt * 32;
        __syncthreads();
        {   // A tile 32x32: one float4 per thread, store transposed [k][row]
            int r = t >> 3, c4 = t & 7;
            float4 v = *(const float4*)(A + (row0 + r) * 128 + kk0 + c4 * 4);
            if (RELU_IN) {
                v.x = fmaxf(v.x, 0.f); v.y = fmaxf(v.y, 0.f);
                v.z = fmaxf(v.z, 0.f); v.w = fmaxf(v.w, 0.f);
            }
            As[(c4 * 4 + 0) * 32 + r] = v.x;
            As[(c4 * 4 + 1) * 32 + r] = v.y;
            As[(c4 * 4 + 2) * 32 + r] = v.z;
            As[(c4 * 4 + 3) * 32 + r] = v.w;
        }
#pragma unroll
        for (int i = 0; i < 4; i++) {
            int f = t + i * 256;
            int kr = f >> 5, c4 = f & 31;
            *(float4*)(Ws + kr * 128 + c4 * 4) =
                *(const float4*)(W + (kk0 + kr) * 128 + c4 * 4);
        }
        __syncthreads();
#pragma unroll
        for (int kk = 0; kk < 32; kk++) {
            ulonglong2 ap = *(const ulonglong2*)(As + kk * 32 + ty * 4);
            float4 w = *(const float4*)(Ws + kk * 128 + tx * 4);
            ull w0 = pack2(w.x, w.x), w1 = pack2(w.y, w.y);
            ull w2 = pack2(w.z, w.z), w3 = pack2(w.w, w.w);
            acc[0][0] = ffma2(ap.x, w0, acc[0][0]);
            acc[0][1] = ffma2(ap.x, w1, acc[0][1]);
            acc[0][2] = ffma2(ap.x, w2, acc[0][2]);
            acc[0][3] = ffma2(ap.x, w3, acc[0][3]);
            acc[1][0] = ffma2(ap.y, w0, acc[1][0]);
            acc[1][1] = ffma2(ap.y, w1, acc[1][1]);
            acc[1][2] = ffma2(ap.y, w2, acc[1][2]);
            acc[1][3] = ffma2(ap.y, w3, acc[1][3]);
        }
    }

    float4 bz = make_float4(0.f, 0.f, 0.f, 0.f);
    if (HAS_BIAS) bz = *(const float4*)(bias + tx * 4);
#pragma unroll
    for (int rp = 0; rp < 2; rp++) {
        float2 c0 = unpack2(acc[rp][0]), c1 = unpack2(acc[rp][1]);
        float2 c2 = unpack2(acc[rp][2]), c3 = unpack2(acc[rp][3]);
#pragma unroll
        for (int e = 0; e < 2; e++) {
            int gr = row0 + ty * 4 + rp * 2 + e;
            float4 o = e ? make_float4(c0.y, c1.y, c2.y, c3.y)
                         : make_float4(c0.x, c1.x, c2.x, c3.x);
            o.x += bz.x; o.y += bz.y; o.z += bz.z; o.w += bz.w;
            if (RELU_OUT) {
                o.x = fmaxf(o.x, 0.f); o.y = fmaxf(o.y, 0.f);
                o.z = fmaxf(o.z, 0.f); o.w = fmaxf(o.w, 0.f);
            }
            if (HAS_ADD) {
                float4 av = *(const float4*)(add + gr * 128 + tx * 4);
                o.x += av.x; o.y += av.y; o.z += av.z; o.w += av.w;
            }
            *(float4*)(C + gr * 128 + tx * 4) = o;
        }
    }
}

// ---------------- dual GEMM: C1=A@W1, C2=A@W2, shared A tile, f32x2 --------
__global__ __launch_bounds__(256) void gemm128_dual(
    const float* __restrict__ A, const float* __restrict__ W1g,
    const float* __restrict__ W2g, float* __restrict__ C1,
    float* __restrict__ C2)
{
    __shared__ __align__(16) float As[32 * 32];
    __shared__ __align__(16) float Ws1[32 * 128];
    __shared__ __align__(16) float Ws2[32 * 128];
    const int t = threadIdx.x;
    const int tx = t & 31;
    const int ty = t >> 5;
    const int row0 = blockIdx.x * 32;

    ull a1[2][4], a2[2][4];
#pragma unroll
    for (int rp = 0; rp < 2; rp++)
#pragma unroll
        for (int c = 0; c < 4; c++) { a1[rp][c] = 0ull; a2[rp][c] = 0ull; }

    for (int kt = 0; kt < 4; kt++) {
        const int kk0 = kt * 32;
        __syncthreads();
        {
            int r = t >> 3, c4 = t & 7;
            float4 v = *(const float4*)(A + (row0 + r) * 128 + kk0 + c4 * 4);
            As[(c4 * 4 + 0) * 32 + r] = v.x;
            As[(c4 * 4 + 1) * 32 + r] = v.y;
            As[(c4 * 4 + 2) * 32 + r] = v.z;
            As[(c4 * 4 + 3) * 32 + r] = v.w;
        }
#pragma unroll
        for (int i = 0; i < 4; i++) {
            int f = t + i * 256;
            int kr = f >> 5, c4 = f & 31;
            *(float4*)(Ws1 + kr * 128 + c4 * 4) =
                *(const float4*)(W1g + (kk0 + kr) * 128 + c4 * 4);
            *(float4*)(Ws2 + kr * 128 + c4 * 4) =
                *(const float4*)(W2g + (kk0 + kr) * 128 + c4 * 4);
        }
        __syncthreads();
#pragma unroll
        for (int kk = 0; kk < 32; kk++) {
            ulonglong2 ap = *(const ulonglong2*)(As + kk * 32 + ty * 4);
            float4 w = *(const float4*)(Ws1 + kk * 128 + tx * 4);
            ull w0 = pack2(w.x, w.x), w1 = pack2(w.y, w.y);
            ull w2 = pack2(w.z, w.z), w3 = pack2(w.w, w.w);
            a1[0][0] = ffma2(ap.x, w0, a1[0][0]);
            a1[0][1] = ffma2(ap.x, w1, a1[0][1]);
            a1[0][2] = ffma2(ap.x, w2, a1[0][2]);
            a1[0][3] = ffma2(ap.x, w3, a1[0][3]);
            a1[1][0] = ffma2(ap.y, w0, a1[1][0]);
            a1[1][1] = ffma2(ap.y, w1, a1[1][1]);
            a1[1][2] = ffma2(ap.y, w2, a1[1][2]);
            a1[1][3] = ffma2(ap.y, w3, a1[1][3]);
            float4 v = *(const float4*)(Ws2 + kk * 128 + tx * 4);
            ull v0 = pack2(v.x, v.x), v1 = pack2(v.y, v.y);
            ull v2 = pack2(v.z, v.z), v3 = pack2(v.w, v.w);
            a2[0][0] = ffma2(ap.x, v0, a2[0][0]);
            a2[0][1] = ffma2(ap.x, v1, a2[0][1]);
            a2[0][2] = ffma2(ap.x, v2, a2[0][2]);
            a2[0][3] = ffma2(ap.x, v3, a2[0][3]);
            a2[1][0] = ffma2(ap.y, v0, a2[1][0]);
            a2[1][1] = ffma2(ap.y, v1, a2[1][1]);
            a2[1][2] = ffma2(ap.y, v2, a2[1][2]);
            a2[1][3] = ffma2(ap.y, v3, a2[1][3]);
        }
    }
#pragma unroll
    for (int rp = 0; rp < 2; rp++) {
        float2 c0 = unpack2(a1[rp][0]), c1 = unpack2(a1[rp][1]);
        float2 c2 = unpack2(a1[rp][2]), c3 = unpack2(a1[rp][3]);
        float2 d0 = unpack2(a2[rp][0]), d1 = unpack2(a2[rp][1]);
        float2 d2 = unpack2(a2[rp][2]), d3 = unpack2(a2[rp][3]);
#pragma unroll
        for (int e = 0; e < 2; e++) {
            int gr = row0 + ty * 4 + rp * 2 + e;
            *(float4*)(C1 + gr * 128 + tx * 4) =
                e ? make_float4(c0.y, c1.y, c2.y, c3.y)
                  : make_float4(c0.x, c1.x, c2.x, c3.x);
            *(float4*)(C2 + gr * 128 + tx * 4) =
                e ? make_float4(d0.y, d1.y, d2.y, d3.y)
                  : make_float4(d0.x, d1.x, d2.x, d3.x);
        }
    }
}

// ---------------- attention: 1 warp/node, coalesced loads + f32x2 ----------
struct __align__(16) WarpSmem {
    float dist[32 * 36];   // [k][d] pad-36
    float seq[32 * 20];    // [k][s] pad-20
    float ud[8 * 32];
    float us[8 * 16];
    float c0[8];
    float lgk[32 * 10];    // [k][h] pad-10 (8B-aligned head pairs)
    float sd[8 * 32];
    float ss[8 * 16];
    int   jb[32];
};

__global__ __launch_bounds__(128) void attn_kernel(
    const float* __restrict__ dist_g, const float* __restrict__ seq_g,
    const int* __restrict__ idx, const float* __restrict__ qg,
    const float* __restrict__ mkg, const float* __restrict__ mvg,
    const float* __restrict__ Wk, const float* __restrict__ bk,
    const float* __restrict__ Wv, const float* __restrict__ bv,
    float* __restrict__ att_out)
{
    __shared__ WarpSmem S[4];
    const int lane = threadIdx.x & 31;
    const int w = threadIdx.x >> 5;
    WarpSmem& s = S[w];
    const int n = blockIdx.x * 4 + w;

    // ---- Phase A: coalesced staging
    const float4 qv = ((const float4*)(qg + (long)n * 128))[lane];
    s.jb[lane] = idx[n * 32 + lane];
    {
        const float4* dg = (const float4*)(dist_g + (long)n * 1024);
#pragma unroll
        for (int it = 0; it < 8; it++) {
            int i4 = it * 32 + lane;
            float4 v = dg[i4];
            float* p = s.dist + (i4 >> 3) * 36 + (i4 & 7) * 4;
            p[0] = v.x; p[1] = v.y; p[2] = v.z; p[3] = v.w;
        }
        const float4* sg = (const float4*)(seq_g + (long)n * 512);
#pragma unroll
        for (int it = 0; it < 4; it++) {
            int i4 = it * 32 + lane;
            float4 v = sg[i4];
            float* p = s.seq + (i4 >> 2) * 20 + (i4 & 3) * 4;
            p[0] = v.x; p[1] = v.y; p[2] = v.z; p[3] = v.w;
        }
    }
    __syncwarp();

    // ---- Phase B: folds ud/us/c0 via coalesced row loads + 4-lane reduce
    const int h4 = lane >> 2;
#pragma unroll 8
    for (int r = 0; r < 48; r++) {
        float4 wv = *(const float4*)(Wk + (long)(128 + r) * 128 + lane * 4);
        float p = wv.x * qv.x + wv.y * qv.y + wv.z * qv.z + wv.w * qv.w;
        p += __shfl_xor_sync(~0u, p, 1);
        p += __shfl_xor_sync(~0u, p, 2);
        if ((lane & 3) == 0) {
            if (r < 32) s.ud[h4 * 32 + r] = p;
            else        s.us[h4 * 16 + (r - 32)] = p;
        }
    }
    {
        float4 wv = *(const float4*)(bk + lane * 4);
        float p = wv.x * qv.x + wv.y * qv.y + wv.z * qv.z + wv.w * qv.w;
        p += __shfl_xor_sync(~0u, p, 1);
        p += __shfl_xor_sync(~0u, p, 2);
        if ((lane & 3) == 0) s.c0[h4] = p;
    }
    __syncwarp();

    // ---- Phase C1: q . mk[jb[k]] (coalesced row load per k + 4-lane reduce)
#pragma unroll 8
    for (int k = 0; k < 32; k++) {
        int j = s.jb[k];
        float4 m = *(const float4*)(mkg + (long)j * 128 + lane * 4);
        float p = m.x * qv.x + m.y * qv.y + m.z * qv.z + m.w * qv.w;
        p += __shfl_xor_sync(~0u, p, 1);
        p += __shfl_xor_sync(~0u, p, 2);
        if ((lane & 3) == 0) s.lgk[k * 10 + h4] = p;
    }
    __syncwarp();

    // ---- Phase C2: dist/seq logit terms (lane = k), f32x2 dots + softmax
    float lg[8];
    {
        ull dr2[16], sq2[8];
#pragma unroll
        for (int i = 0; i < 8; i++) {      // 8 x ulonglong2 = 32 floats
            ulonglong2 v = ((const ulonglong2*)(s.dist + lane * 36))[i];
            dr2[2 * i] = v.x; dr2[2 * i + 1] = v.y;
        }
#pragma unroll
        for (int i = 0; i < 4; i++) {      // 4 x ulonglong2 = 16 floats
            ulonglong2 v = ((const ulonglong2*)(s.seq + lane * 20))[i];
            sq2[2 * i] = v.x; sq2[2 * i + 1] = v.y;
        }
#pragma unroll
        for (int h = 0; h < 8; h++) {
            ull acc2 = 0ull;
#pragma unroll
            for (int i = 0; i < 8; i++) {
                ulonglong2 u = ((const ulonglong2*)(s.ud + h * 32))[i];
                acc2 = ffma2(dr2[2 * i], u.x, acc2);
                acc2 = ffma2(dr2[2 * i + 1], u.y, acc2);
            }
#pragma unroll
            for (int i = 0; i < 4; i++) {
                ulonglong2 u = ((const ulonglong2*)(s.us + h * 16))[i];
                acc2 = ffma2(sq2[2 * i], u.x, acc2);
                acc2 = ffma2(sq2[2 * i + 1], u.y, acc2);
            }
            float2 p = unpack2(acc2);
            lg[h] = 0.25f * (s.lgk[lane * 10 + h] + p.x + p.y + s.c0[h]);
        }
    }
#pragma unroll
    for (int h = 0; h < 8; h++) {
        float m = lg[h];
#pragma unroll
        for (int o = 16; o > 0; o >>= 1) m = fmaxf(m, __shfl_xor_sync(~0u, m, o));
        float e = __expf(lg[h] - m);
        float sm = e;
#pragma unroll
        for (int o = 16; o > 0; o >>= 1) sm += __shfl_xor_sync(~0u, sm, o);
        s.lgk[lane * 10 + h] = e / sm;
    }
    __syncwarp();

    // ---- Phase D: weighted sums
    const int sidx = lane & 15;
    float4 acc = make_float4(0.f, 0.f, 0.f, 0.f);
    ull sdl2[4] = {0ull, 0ull, 0ull, 0ull};
    float ssl[4] = {0.f, 0.f, 0.f, 0.f};
#pragma unroll 4
    for (int k = 0; k < 32; k++) {
        int j = s.jb[k];
        float a = s.lgk[k * 10 + h4];
        float4 mv = *(const float4*)(mvg + (long)j * 128 + lane * 4);
        acc.x += a * mv.x; acc.y += a * mv.y;
        acc.z += a * mv.z; acc.w += a * mv.w;
        float dv = s.dist[k * 36 + lane];
        ull dv2 = pack2(dv, dv);
        const ull* ap = (const ull*)(s.lgk + k * 10);
#pragma unroll
        for (int r = 0; r < 4; r++) sdl2[r] = ffma2(ap[r], dv2, sdl2[r]);
        float sv = s.seq[k * 20 + sidx];
#pragma unroll
        for (int r = 0; r < 4; r++) {
            int h2 = (lane >> 4) + 2 * r;
            ssl[r] += s.lgk[k * 10 + h2] * sv;
        }
    }
#pragma unroll
    for (int r = 0; r < 4; r++) {
        float2 p = unpack2(sdl2[r]);
        s.sd[(2 * r) * 32 + lane] = p.x;
        s.sd[(2 * r + 1) * 32 + lane] = p.y;
    }
#pragma unroll
    for (int r = 0; r < 4; r++) s.ss[lane + 32 * r] = ssl[r];
    __syncwarp();

    // ---- Phase D2: outv = acc + sd @ WvD + ss @ WvS + bv (f32x2)
    {
        const int i0 = lane * 4;
        float4 bvv = *(const float4*)(bv + i0);
        ull o01 = pack2(bvv.x + acc.x, bvv.y + acc.y);
        ull o23 = pack2(bvv.z + acc.z, bvv.w + acc.w);
#pragma unroll 8
        for (int d = 0; d < 32; d++) {
            float sdv = s.sd[h4 * 32 + d];
            ull s2 = pack2(sdv, sdv);
            ulonglong2 wv = *(const ulonglong2*)(Wv + (long)(128 + d) * 128 + i0);
            o01 = ffma2(wv.x, s2, o01);
            o23 = ffma2(wv.y, s2, o23);
        }
#pragma unroll 8
        for (int j = 0; j < 16; j++) {
            float ssv = s.ss[h4 * 16 + j];
            ull s2 = pack2(ssv, ssv);
            ulonglong2 wv = *(const ulonglong2*)(Wv + (long)(160 + j) * 128 + i0);
            o01 = ffma2(wv.x, s2, o01);
            o23 = ffma2(wv.y, s2, o23);
        }
        float2 p0 = unpack2(o01), p1 = unpack2(o23);
        *(float4*)(att_out + (long)n * 128 + i0) =
            make_float4(p0.x, p0.y, p1.x, p1.y);
    }
}

// ---------------- launch ----------------
extern "C" void kernel_launch(void* const* d_in, const int* in_sizes, int n_in,
                              void* d_out, int out_size)
{
    const float* features = (const float*)d_in[0];
    const float* distances = (const float*)d_in[1];
    const float* sequence = (const float*)d_in[2];
    const float* encoder = (const float*)d_in[3];
    const int*   idx = (const int*)d_in[4];
    const float* W1 = (const float*)d_in[5];
    const float* b1 = (const float*)d_in[6];
    const float* W2 = (const float*)d_in[7];
    const float* b2 = (const float*)d_in[8];
    const float* W3 = (const float*)d_in[9];
    const float* b3 = (const float*)d_in[10];
    const float* Wq = (const float*)d_in[11];
    const float* bq = (const float*)d_in[12];
    const float* Wk = (const float*)d_in[13];
    const float* bk = (const float*)d_in[14];
    const float* Wv = (const float*)d_in[15];
    const float* bv = (const float*)d_in[16];
    const float* Wo = (const float*)d_in[17];
    const float* bo = (const float*)d_in[18];

    float *h1, *h2, *msg, *q, *mk, *mv, *att;
    cudaGetSymbolAddress((void**)&h1, g_h1);
    cudaGetSymbolAddress((void**)&h2, g_h2);
    cudaGetSymbolAddress((void**)&msg, g_msg);
    cudaGetSymbolAddress((void**)&q, g_q);
    cudaGetSymbolAddress((void**)&mk, g_mk);
    cudaGetSymbolAddress((void**)&mv, g_mv);
    cudaGetSymbolAddress((void**)&att, g_att);

    const int gb = N_NODES / 32;  // 512 blocks
    gemm128<1, 1, 1, 0><<<gb, 256>>>(features, W1, b1, nullptr, h1);
    gemm128<0, 1, 1, 0><<<gb, 256>>>(h1, W2, b2, nullptr, h2);
    gemm128<0, 1, 1, 1><<<gb, 256>>>(h2, W3, b3, encoder, msg);
    gemm128<0, 0, 1, 0><<<gb, 256>>>(features, Wq, bq, nullptr, q);
    gemm128_dual<<<gb, 256>>>(msg, Wk, Wv, mk, mv);
    attn_kernel<<<N_NODES / 4, 128>>>(distances, sequence, idx,
                                      q, mk, mv, Wk, bk, Wv, bv, att);
    gemm128<0, 0, 1, 1><<<gb, 256>>>(att, Wo, bo, features, (float*)d_out);
}